// round 11
// baseline (speedup 1.0000x reference)
#include <cuda_runtime.h>
#include <cuda_bf16.h>
#include <stdint.h>
#include <math.h>

#define Bdim 2
#define Tdim 2048
#define Cdim 1024
#define Hdim 16
#define HDdim 64
#define QSCALE 0.125f   // (1/ALPHA/sqrt(HD)) * ALPHA == 1/sqrt(64)
#define NEGINF __int_as_float(0xff800000)

#define Mrows (Bdim * Tdim)   // 4096

// ---------------- device scratch (no allocation allowed) -------------------
__device__ float g_q[Mrows * Cdim];
__device__ float g_k[Mrows * Cdim];
__device__ float g_vt[Cdim * Mrows];                  // V^T: [C][B*T]
__device__ __nv_bfloat16 g_ah[3][Mrows * Cdim];       // activation hi (q,k,v in; slot0 reused for attn out)
__device__ __nv_bfloat16 g_al[3][Mrows * Cdim];       // activation lo
__device__ __nv_bfloat16 g_wh[4][Cdim * Cdim];        // W^T hi (q,k,v,p)
__device__ __nv_bfloat16 g_wl[4][Cdim * Cdim];        // W^T lo

// ---------------------------------------------------------------------------
// Portable PTX helpers (compute_103 virtual arch safe)
// ---------------------------------------------------------------------------
__device__ __forceinline__ void cp16(uint32_t dst, const void* src) {
    asm volatile("cp.async.cg.shared.global [%0], [%1], 16;" :: "r"(dst), "l"(src));
}
__device__ __forceinline__ void cp_commit() {
    asm volatile("cp.async.commit_group;" ::: "memory");
}
template <int N>
__device__ __forceinline__ void cp_wait() {
    asm volatile("cp.async.wait_group %0;" :: "n"(N) : "memory");
}
__device__ __forceinline__ void ldm_x4(uint32_t f[4], uint32_t addr) {
    asm volatile("ldmatrix.sync.aligned.m8n8.x4.shared.b16 {%0,%1,%2,%3}, [%4];"
                 : "=r"(f[0]), "=r"(f[1]), "=r"(f[2]), "=r"(f[3]) : "r"(addr));
}
__device__ __forceinline__ void mma_bf16(float c[4], const uint32_t a[4],
                                         const uint32_t b0, const uint32_t b1) {
    asm volatile(
        "mma.sync.aligned.m16n8k16.row.col.f32.bf16.bf16.f32 "
        "{%0,%1,%2,%3}, {%4,%5,%6,%7}, {%8,%9}, {%0,%1,%2,%3};"
        : "+f"(c[0]), "+f"(c[1]), "+f"(c[2]), "+f"(c[3])
        : "r"(a[0]), "r"(a[1]), "r"(a[2]), "r"(a[3]), "r"(b0), "r"(b1));
}
__device__ __forceinline__ void mma_tf32(float c[4], uint32_t a0, uint32_t a1,
                                         uint32_t a2, uint32_t a3,
                                         uint32_t b0, uint32_t b1) {
    asm volatile(
        "mma.sync.aligned.m16n8k8.row.col.f32.tf32.tf32.f32 "
        "{%0,%1,%2,%3}, {%4,%5,%6,%7}, {%8,%9}, {%0,%1,%2,%3};"
        : "+f"(c[0]), "+f"(c[1]), "+f"(c[2]), "+f"(c[3])
        : "r"(a0), "r"(a1), "r"(a2), "r"(a3), "r"(b0), "r"(b1));
}
__device__ __forceinline__ float tf32r(float x) {
    uint32_t u;
    asm("cvt.rna.tf32.f32 %0, %1;" : "=r"(u) : "f"(x));
    return __uint_as_float(u);
}
__device__ __forceinline__ uint32_t tf32u(float x) {
    uint32_t u;
    asm("cvt.rna.tf32.f32 %0, %1;" : "=r"(u) : "f"(x));
    return u;
}
__device__ __forceinline__ uint32_t bfpack(float x, float y) {
    return (uint32_t)__bfloat16_as_ushort(__float2bfloat16_rn(x)) |
           ((uint32_t)__bfloat16_as_ushort(__float2bfloat16_rn(y)) << 16);
}

// ---------------------------------------------------------------------------
// Batched conversion kernels
// ---------------------------------------------------------------------------
// splits 3 fp32 activation tensors into bf16 hi/lo; 2 float4 per thread
__global__ __launch_bounds__(256) void conv_split3_kernel(
    const float* __restrict__ x0, const float* __restrict__ x1,
    const float* __restrict__ x2,
    __nv_bfloat16* __restrict__ h0, __nv_bfloat16* __restrict__ l0,
    __nv_bfloat16* __restrict__ h1, __nv_bfloat16* __restrict__ l1,
    __nv_bfloat16* __restrict__ h2, __nv_bfloat16* __restrict__ l2)
{
    const float* x = (blockIdx.y == 0) ? x0 : (blockIdx.y == 1) ? x1 : x2;
    __nv_bfloat16* h = (blockIdx.y == 0) ? h0 : (blockIdx.y == 1) ? h1 : h2;
    __nv_bfloat16* l = (blockIdx.y == 0) ? l0 : (blockIdx.y == 1) ? l1 : l2;
    int i0 = blockIdx.x * 512 + threadIdx.x;
#pragma unroll
    for (int rep = 0; rep < 2; rep++) {
        int i = i0 + rep * 256;
        float4 v = ((const float4*)x)[i];
        union { __nv_bfloat16 b[4]; uint2 u; } H, L;
        float vv[4] = {v.x, v.y, v.z, v.w};
#pragma unroll
        for (int j = 0; j < 4; j++) {
            H.b[j] = __float2bfloat16_rn(vv[j]);
            L.b[j] = __float2bfloat16_rn(vv[j] - __bfloat162float(H.b[j]));
        }
        ((uint2*)h)[i] = H.u;
        ((uint2*)l)[i] = L.u;
    }
}

// W [K,N] fp32 -> W^T hi/lo bf16 [N,K], 4 weight matrices in one launch
__global__ __launch_bounds__(256) void conv_wT4_kernel(
    const float* __restrict__ W0, const float* __restrict__ W1,
    const float* __restrict__ W2, const float* __restrict__ W3,
    __nv_bfloat16* __restrict__ hB, __nv_bfloat16* __restrict__ lB)
{
    const int wsel = blockIdx.z;
    const float* W = (wsel == 0) ? W0 : (wsel == 1) ? W1 : (wsel == 2) ? W2 : W3;
    __nv_bfloat16* ht = hB + (size_t)wsel * Cdim * Cdim;
    __nv_bfloat16* lt = lB + (size_t)wsel * Cdim * Cdim;
    __shared__ float t[32][33];
    int n0 = blockIdx.x * 32, k0 = blockIdx.y * 32;
    int tx = threadIdx.x, ty = threadIdx.y;
#pragma unroll
    for (int r = 0; r < 32; r += 8)
        t[ty + r][tx] = W[(size_t)(k0 + ty + r) * Cdim + n0 + tx];
    __syncthreads();
#pragma unroll
    for (int r = 0; r < 32; r += 8) {
        float v = t[tx][ty + r];
        __nv_bfloat16 hb = __float2bfloat16_rn(v);
        size_t o = (size_t)(n0 + ty + r) * Cdim + k0 + tx;
        ht[o] = hb;
        lt[o] = __float2bfloat16_rn(v - __bfloat162float(hb));
    }
}

// ---------------------------------------------------------------------------
// HMMA bf16x3 GEMM, 3-stage cp.async pipeline, one sync per K-chunk.
// C[M,N] = (Ah+Al)[M,K] @ (Bh+Bl)^T[N,K] + bias;  ldc / bias_mode params
// ---------------------------------------------------------------------------
#define BM 128
#define BN 128
#define BKc 32
#define LDT 40
#define TILE_B (128 * LDT * 2)
#define STG_B (4 * TILE_B)            // 40960
#define OFF_AH 0
#define OFF_AL TILE_B
#define OFF_BH (2 * TILE_B)
#define OFF_BL (3 * TILE_B)
#define GEMM_SMEM (3 * STG_B)         // 122880
#define NKCH (Cdim / BKc)             // 32

extern __shared__ __align__(128) char gsm[];

__global__ __launch_bounds__(256) void gemm_tc_kernel(
    const __nv_bfloat16* __restrict__ Ah, const __nv_bfloat16* __restrict__ Al,
    const __nv_bfloat16* __restrict__ Bh, const __nv_bfloat16* __restrict__ Bl,
    const float* __restrict__ bias, float* __restrict__ Cout,
    float oscale, int oround, int bias_mode, int ldc)
{
    const int tid = threadIdx.x;
    const int lane = tid & 31;
    const int wid = tid >> 5;
    const int wm = wid >> 2;
    const int wn = wid & 3;
    const int m0 = blockIdx.y * BM;
    const int n0 = blockIdx.x * BN;
    const uint32_t sb = (uint32_t)__cvta_generic_to_shared(gsm);

    const __nv_bfloat16* srcA[2] = {Ah, Al};
    const __nv_bfloat16* srcB[2] = {Bh, Bl};

    auto load_stage = [&](int c, int st) {
        const int kc = c * BKc;
        const uint32_t base = sb + st * STG_B;
#pragma unroll
        for (int it = 0; it < 8; it++) {
            int id = tid + it * 256;
            int tile = id >> 9;
            int rem = id & 511;
            int row = rem >> 2;
            int grp = rem & 3;
            uint32_t dst = base + tile * TILE_B + (row * LDT + grp * 8) * 2;
            const __nv_bfloat16* s;
            if (tile < 2) s = srcA[tile] + (size_t)(m0 + row) * Cdim + kc + grp * 8;
            else          s = srcB[tile - 2] + (size_t)(n0 + row) * Cdim + kc + grp * 8;
            cp16(dst, s);
        }
        cp_commit();
    };

    float acc[4][4][4];
#pragma unroll
    for (int i = 0; i < 4; i++)
#pragma unroll
        for (int j = 0; j < 4; j++)
#pragma unroll
            for (int r = 0; r < 4; r++) acc[i][j][r] = 0.0f;

    const int a_r = lane & 15, a_cg = lane >> 4;
    const int b_nt = lane >> 4, b_half = (lane >> 3) & 1, b_r = lane & 7;

    load_stage(0, 0);
    load_stage(1, 1);

    int st = 0;
    for (int c = 0; c < NKCH; ++c) {
        if (c + 1 < NKCH) cp_wait<1>();
        else              cp_wait<0>();
        __syncthreads();                           // stage st ready; stage (c+2)%3 free
        if (c + 2 < NKCH) {
            int nst = st + 2; if (nst >= 3) nst -= 3;
            load_stage(c + 2, nst);
        }

        const uint32_t stg = sb + st * STG_B;
        const uint32_t tAH = stg + OFF_AH, tAL = stg + OFF_AL;
        const uint32_t tBH = stg + OFF_BH, tBL = stg + OFF_BL;

#pragma unroll
        for (int ks = 0; ks < 2; ks++) {
            const int k16 = ks * 16;
            uint32_t bAddrOff[2];
#pragma unroll
            for (int bj = 0; bj < 2; bj++)
                bAddrOff[bj] = (uint32_t)(((wn * 32 + bj * 16 + b_nt * 8 + b_r) * LDT
                                           + k16 + b_half * 8) * 2);
            uint32_t aAddrOff[4];
#pragma unroll
            for (int mi = 0; mi < 4; mi++)
                aAddrOff[mi] = (uint32_t)(((wm * 64 + mi * 16 + a_r) * LDT
                                           + k16 + a_cg * 8) * 2);

            uint32_t aH[4][4];
#pragma unroll
            for (int mi = 0; mi < 4; mi++) ldm_x4(aH[mi], tAH + aAddrOff[mi]);
            uint32_t bH[2][4];
#pragma unroll
            for (int bj = 0; bj < 2; bj++) ldm_x4(bH[bj], tBH + bAddrOff[bj]);
#pragma unroll
            for (int mi = 0; mi < 4; mi++)
#pragma unroll
                for (int bj = 0; bj < 2; bj++) {
                    mma_bf16(acc[mi][bj * 2 + 0], aH[mi], bH[bj][0], bH[bj][1]);
                    mma_bf16(acc[mi][bj * 2 + 1], aH[mi], bH[bj][2], bH[bj][3]);
                }
            uint32_t bL[2][4];
#pragma unroll
            for (int bj = 0; bj < 2; bj++) ldm_x4(bL[bj], tBL + bAddrOff[bj]);
#pragma unroll
            for (int mi = 0; mi < 4; mi++)
#pragma unroll
                for (int bj = 0; bj < 2; bj++) {
                    mma_bf16(acc[mi][bj * 2 + 0], aH[mi], bL[bj][0], bL[bj][1]);
                    mma_bf16(acc[mi][bj * 2 + 1], aH[mi], bL[bj][2], bL[bj][3]);
                }
            uint32_t aL[4][4];
#pragma unroll
            for (int mi = 0; mi < 4; mi++) ldm_x4(aL[mi], tAL + aAddrOff[mi]);
#pragma unroll
            for (int mi = 0; mi < 4; mi++)
#pragma unroll
                for (int bj = 0; bj < 2; bj++) {
                    mma_bf16(acc[mi][bj * 2 + 0], aL[mi], bH[bj][0], bH[bj][1]);
                    mma_bf16(acc[mi][bj * 2 + 1], aL[mi], bH[bj][2], bH[bj][3]);
                }
        }
        if (++st == 3) st = 0;
    }

    const int er = lane >> 2, ec = (lane & 3) * 2;
#pragma unroll
    for (int mi = 0; mi < 4; mi++) {
#pragma unroll
        for (int j = 0; j < 4; j++) {
            int col = n0 + wn * 32 + j * 8 + ec;
            int r0 = m0 + wm * 64 + mi * 16 + er;
            float b0c, b1c, b0r, b1r;
            if (bias_mode == 0) {
                b0c = __ldg(bias + col); b1c = __ldg(bias + col + 1);
                b0r = b0c; b1r = b1c;
                float2 o0, o1;
                o0.x = acc[mi][j][0] + b0c; o0.y = acc[mi][j][1] + b1c;
                o1.x = acc[mi][j][2] + b0r; o1.y = acc[mi][j][3] + b1r;
                if (oround) {
                    o0.x = tf32r(o0.x * oscale); o0.y = tf32r(o0.y * oscale);
                    o1.x = tf32r(o1.x * oscale); o1.y = tf32r(o1.y * oscale);
                }
                *(float2*)&Cout[(size_t)r0 * ldc + col] = o0;
                *(float2*)&Cout[(size_t)(r0 + 8) * ldc + col] = o1;
            } else {
                float br0 = __ldg(bias + r0), br8 = __ldg(bias + r0 + 8);
                float2 o0, o1;
                o0.x = acc[mi][j][0] + br0; o0.y = acc[mi][j][1] + br0;
                o1.x = acc[mi][j][2] + br8; o1.y = acc[mi][j][3] + br8;
                if (oround) {
                    o0.x = tf32r(o0.x * oscale); o0.y = tf32r(o0.y * oscale);
                    o1.x = tf32r(o1.x * oscale); o1.y = tf32r(o1.y * oscale);
                }
                *(float2*)&Cout[(size_t)r0 * ldc + col] = o0;
                *(float2*)&Cout[(size_t)(r0 + 8) * ldc + col] = o1;
            }
        }
    }
}

// ---------------------------------------------------------------------------
// Flash attention (causal), tf32 tensor cores, 3-stage KV pipeline.
// CTA: 128 q-rows x one (head,batch); 8 warps x 16 rows; BK=64 keys/iter.
// VT layout: [C][B*T].  Epilogue writes bf16 hi/lo splits directly.
// ---------------------------------------------------------------------------
#define FBQ 128
#define FBK 64
#define LDF 68
#define FQ_BYTES (FBQ * LDF * 4)          // 34816
#define FK_BYTES (FBK * LDF * 4)          // 17408
#define FSTG (2 * FK_BYTES)               // K + VT per stage
#define FLASH_SMEM (FQ_BYTES + 3 * FSTG)  // 139264

__global__ __launch_bounds__(256, 1) void flash_tc_kernel(
    const float* __restrict__ Q, const float* __restrict__ Kg,
    const float* __restrict__ VT,
    __nv_bfloat16* __restrict__ Yh, __nv_bfloat16* __restrict__ Yl)
{
    const int tid = threadIdx.x;
    const int lane = tid & 31;
    const int wid = tid >> 5;
    const int qt = gridDim.x - 1 - blockIdx.x;
    const int h = blockIdx.y;
    const int b = blockIdx.z;
    const int qb = qt * FBQ;
    const uint32_t sb = (uint32_t)__cvta_generic_to_shared(gsm);

    const int laneRow = (lane & 7) + 8 * (lane >> 4);
    const uint32_t laneCol = 16u * ((lane >> 3) & 1);
    const int lq = lane & 3;
    const int lr = lane >> 2;

    // ---- load Q tile (group 0) ----
#pragma unroll
    for (int it = 0; it < 8; it++) {
        int id = tid + it * 256;
        int row = id >> 4, j = id & 15;
        cp16(sb + (uint32_t)(row * LDF + 4 * j) * 4,
             Q + ((size_t)b * Tdim + qb + row) * Cdim + h * HDdim + 4 * j);
    }
    cp_commit();

    const uint32_t stage0 = sb + FQ_BYTES;

    auto load_kv = [&](int kt, int st) {
        const int k0 = kt * FBK;
        const uint32_t base = stage0 + st * FSTG;
#pragma unroll
        for (int it = 0; it < 8; it++) {
            int id = tid + it * 256;
            int tile = id >> 10;
            int rem = id & 1023;
            int row = rem >> 4, j = rem & 15;
            uint32_t dst = base + tile * FK_BYTES + (uint32_t)(row * LDF + 4 * j) * 4;
            const float* src;
            if (tile == 0)
                src = Kg + ((size_t)b * Tdim + k0 + row) * Cdim + h * HDdim + 4 * j;
            else
                src = VT + (size_t)(h * HDdim + row) * Mrows + b * Tdim + k0 + 4 * j;
            cp16(dst, src);
        }
        cp_commit();
    };

    const int nkt = 2 * qt + 2;
    load_kv(0, 0);
    if (nkt > 1) load_kv(1, 1);

    cp_wait<2>();           // Q arrived (kv0/kv1 may be in flight)
    __syncthreads();
    uint32_t qf[8][4];
    {
        uint32_t qbase = sb + (uint32_t)((16 * wid + laneRow) * LDF) * 4 + laneCol;
#pragma unroll
        for (int g = 0; g < 8; g++) ldm_x4(qf[g], qbase + 32 * g);
    }

    float oA[8][4];
#pragma unroll
    for (int nt = 0; nt < 8; nt++)
#pragma unroll
        for (int r = 0; r < 4; r++) oA[nt][r] = 0.0f;
    float m0 = NEGINF, m1 = NEGINF, l0 = 0.0f, l1 = 0.0f;

    const int qw0 = qb + 16 * wid;

    int st = 0;
    for (int kt = 0; kt < nkt; kt++) {
        if (kt + 1 < nkt) cp_wait<1>();
        else              cp_wait<0>();
        __syncthreads();                       // stage st ready; stage (kt+2)%3 free
        if (kt + 2 < nkt) {
            int nst = st + 2; if (nst >= 3) nst -= 3;
            load_kv(kt + 2, nst);
        }

        const int k0 = kt * FBK;
        if (k0 <= qw0 + 15) {
            const uint32_t kst = stage0 + st * FSTG;
            const uint32_t vst = kst + FK_BYTES;

            float s[8][4];
#pragma unroll
            for (int nt = 0; nt < 8; nt++)
#pragma unroll
                for (int r = 0; r < 4; r++) s[nt][r] = 0.0f;

#pragma unroll
            for (int g = 0; g < 8; g++) {
#pragma unroll
                for (int ntp = 0; ntp < 4; ntp++) {
                    uint32_t kb[4];
                    ldm_x4(kb, kst + (uint32_t)((16 * ntp + laneRow) * LDF) * 4
                               + 32 * g + laneCol);
                    mma_tf32(s[2 * ntp],     qf[g][0], qf[g][2], qf[g][1], qf[g][3],
                             kb[0], kb[1]);
                    mma_tf32(s[2 * ntp + 1], qf[g][0], qf[g][2], qf[g][1], qf[g][3],
                             kb[2], kb[3]);
                }
            }

            if (k0 + FBK - 1 > qw0) {
#pragma unroll
                for (int nt = 0; nt < 8; nt++)
#pragma unroll
                    for (int r = 0; r < 4; r++) {
                        int col = k0 + 8 * nt + 2 * lq + (r & 1);
                        int row = qw0 + lr + 8 * (r >> 1);
                        if (col > row) s[nt][r] = NEGINF;
                    }
            }

            float mx0 = NEGINF, mx1 = NEGINF;
#pragma unroll
            for (int nt = 0; nt < 8; nt++) {
                mx0 = fmaxf(mx0, fmaxf(s[nt][0], s[nt][1]));
                mx1 = fmaxf(mx1, fmaxf(s[nt][2], s[nt][3]));
            }
            mx0 = fmaxf(mx0, __shfl_xor_sync(0xffffffffu, mx0, 1));
            mx0 = fmaxf(mx0, __shfl_xor_sync(0xffffffffu, mx0, 2));
            mx1 = fmaxf(mx1, __shfl_xor_sync(0xffffffffu, mx1, 1));
            mx1 = fmaxf(mx1, __shfl_xor_sync(0xffffffffu, mx1, 2));
            float mn0 = fmaxf(m0, mx0), mn1 = fmaxf(m1, mx1);
            float c0 = __expf(m0 - mn0), c1 = __expf(m1 - mn1);
            float rs0 = 0.0f, rs1 = 0.0f;
#pragma unroll
            for (int nt = 0; nt < 8; nt++) {
                oA[nt][0] *= c0; oA[nt][1] *= c0;
                oA[nt][2] *= c1; oA[nt][3] *= c1;
                s[nt][0] = __expf(s[nt][0] - mn0);
                s[nt][1] = __expf(s[nt][1] - mn0);
                s[nt][2] = __expf(s[nt][2] - mn1);
                s[nt][3] = __expf(s[nt][3] - mn1);
                rs0 += s[nt][0] + s[nt][1];
                rs1 += s[nt][2] + s[nt][3];
            }
            rs0 += __shfl_xor_sync(0xffffffffu, rs0, 1);
            rs0 += __shfl_xor_sync(0xffffffffu, rs0, 2);
            rs1 += __shfl_xor_sync(0xffffffffu, rs1, 1);
            rs1 += __shfl_xor_sync(0xffffffffu, rs1, 2);
            l0 = l0 * c0 + rs0;
            l1 = l1 * c1 + rs1;
            m0 = mn0; m1 = mn1;

            const int srcA0 = (lane & ~3) | (lq >> 1);
            const int srcA2 = srcA0 + 2;
            const bool odd = (lane & 1);
#pragma unroll
            for (int g = 0; g < 8; g++) {
                uint32_t p0 = tf32u(s[g][0]), p1 = tf32u(s[g][1]);
                uint32_t p2 = tf32u(s[g][2]), p3 = tf32u(s[g][3]);
                uint32_t e, o;
                e = __shfl_sync(0xffffffffu, p0, srcA0);
                o = __shfl_sync(0xffffffffu, p1, srcA0);
                uint32_t a0 = odd ? o : e;
                e = __shfl_sync(0xffffffffu, p2, srcA0);
                o = __shfl_sync(0xffffffffu, p3, srcA0);
                uint32_t a1 = odd ? o : e;
                e = __shfl_sync(0xffffffffu, p0, srcA2);
                o = __shfl_sync(0xffffffffu, p1, srcA2);
                uint32_t a2 = odd ? o : e;
                e = __shfl_sync(0xffffffffu, p2, srcA2);
                o = __shfl_sync(0xffffffffu, p3, srcA2);
                uint32_t a3 = odd ? o : e;
#pragma unroll
                for (int ntp = 0; ntp < 4; ntp++) {
                    uint32_t vb[4];
                    ldm_x4(vb, vst + (uint32_t)((16 * ntp + laneRow) * LDF) * 4
                               + 32 * g + laneCol);
                    mma_tf32(oA[2 * ntp],     a0, a1, a2, a3, vb[0], vb[1]);
                    mma_tf32(oA[2 * ntp + 1], a0, a1, a2, a3, vb[2], vb[3]);
                }
            }
        }
        if (++st == 3) st = 0;
    }

    // ---- epilogue: O/l, split to bf16 hi/lo for the out-projection ----
    float inv0 = 1.0f / l0, inv1 = 1.0f / l1;
    int row0 = qw0 + lr;
    int row1 = row0 + 8;
#pragma unroll
    for (int nt = 0; nt < 8; nt++) {
        int col = h * HDdim + 8 * nt + 2 * lq;
        float w0x = oA[nt][0] * inv0, w0y = oA[nt][1] * inv0;
        float w1x = oA[nt][2] * inv1, w1y = oA[nt][3] * inv1;
        float h0x = __bfloat162float(__float2bfloat16_rn(w0x));
        float h0y = __bfloat162float(__float2bfloat16_rn(w0y));
        float h1x = __bfloat162float(__float2bfloat16_rn(w1x));
        float h1y = __bfloat162float(__float2bfloat16_rn(w1y));
        size_t o0 = ((size_t)b * Tdim + row0) * Cdim + col;
        size_t o1 = ((size_t)b * Tdim + row1) * Cdim + col;
        *(uint32_t*)&Yh[o0] = bfpack(w0x, w0y);
        *(uint32_t*)&Yl[o0] = bfpack(w0x - h0x, w0y - h0y);
        *(uint32_t*)&Yh[o1] = bfpack(w1x, w1y);
        *(uint32_t*)&Yl[o1] = bfpack(w1x - h1x, w1y - h1y);
    }
}

// ---------------------------------------------------------------------------
// Launch
// ---------------------------------------------------------------------------
extern "C" void kernel_launch(void* const* d_in, const int* in_sizes, int n_in,
                              void* d_out, int out_size)
{
    const float* query = (const float*)d_in[0];
    const float* key_  = (const float*)d_in[1];
    const float* value = (const float*)d_in[2];
    const float* Wq = (const float*)d_in[4];
    const float* bq = (const float*)d_in[5];
    const float* Wk = (const float*)d_in[6];
    const float* bk = (const float*)d_in[7];
    const float* Wv = (const float*)d_in[8];
    const float* bv = (const float*)d_in[9];
    const float* Wp = (const float*)d_in[10];
    const float* bp = (const float*)d_in[11];
    float* out = (float*)d_out;

    float *q, *k, *vt;
    __nv_bfloat16 *ah, *al, *wh, *wl;
    cudaGetSymbolAddress((void**)&q,  g_q);
    cudaGetSymbolAddress((void**)&k,  g_k);
    cudaGetSymbolAddress((void**)&vt, g_vt);
    cudaGetSymbolAddress((void**)&ah, g_ah);
    cudaGetSymbolAddress((void**)&al, g_al);
    cudaGetSymbolAddress((void**)&wh, g_wh);
    cudaGetSymbolAddress((void**)&wl, g_wl);

    const size_t AS = (size_t)Mrows * Cdim;   // activation slot elems
    const size_t WS = (size_t)Cdim * Cdim;    // weight slot elems
    __nv_bfloat16 *ah0 = ah, *ah1 = ah + AS, *ah2 = ah + 2 * AS;
    __nv_bfloat16 *al0 = al, *al1 = al + AS, *al2 = al + 2 * AS;

    cudaFuncSetAttribute(gemm_tc_kernel,
                         cudaFuncAttributeMaxDynamicSharedMemorySize, GEMM_SMEM);
    cudaFuncSetAttribute(flash_tc_kernel,
                         cudaFuncAttributeMaxDynamicSharedMemorySize, FLASH_SMEM);

    // 1) all conversions up front
    conv_split3_kernel<<<dim3(Mrows * Cdim / 2048, 3), 256>>>(
        query, key_, value, ah0, al0, ah1, al1, ah2, al2);
    conv_wT4_kernel<<<dim3(32, 32, 4), dim3(32, 8)>>>(Wq, Wk, Wv, Wp, wh, wl);

    // 2) projections
    dim3 ggrid(Cdim / BN, Mrows / BM);          // (8, 32)
    gemm_tc_kernel<<<ggrid, 256, GEMM_SMEM>>>(
        ah0, al0, wh, wl, bq, q, QSCALE, 1, 0, Cdim);
    gemm_tc_kernel<<<ggrid, 256, GEMM_SMEM>>>(
        ah1, al1, wh + WS, wl + WS, bk, k, 1.0f, 1, 0, Cdim);
    // V transposed: vt[C][B*T] = Wv^T @ X^T ; A = Wv^T split, B = X split, row bias
    dim3 vgrid(Mrows / BN, Cdim / BM);          // (32, 8)
    gemm_tc_kernel<<<vgrid, 256, GEMM_SMEM>>>(
        wh + 2 * WS, wl + 2 * WS, ah2, al2, bv, vt, 1.0f, 1, 1, Mrows);

    // 3) attention (writes bf16 hi/lo of output directly into slot 0)
    flash_tc_kernel<<<dim3(Tdim / FBQ, Hdim, Bdim), 256, FLASH_SMEM>>>(
        q, k, vt, ah0, al0);

    // 4) output projection
    gemm_tc_kernel<<<ggrid, 256, GEMM_SMEM>>>(
        ah0, al0, wh + 3 * WS, wl + 3 * WS, bp, out, 1.0f, 0, 0, Cdim);
}